// round 1
// baseline (speedup 1.0000x reference)
#include <cuda_runtime.h>

// Analytic collapse of the reference:
//   y   = a*Hadamard2D(x) + b        (channel block is affine, a = dot(out_w, conv_w),
//                                     b = dot(out_w, conv_b) + out_b)
//   out = Hadamard2D(y) = a*x + b*(H J H^T) = a*x + 256*b*e0e0^T per 256x256 patch
// since _H_MAT is symmetric and _H_MAT @ _H_MAT = I.
//
// => out[e] = a*x[e], plus 256*b added where (h % 256 == 0 && w % 256 == 0).
// With W = 2048, the corner condition on the flat index e is
// (e & 0xFF) == 0  (w % 256)  and  ((e >> 11) & 0xFF) == 0  (h % 256),
// i.e. (e & 0x7F8FF) == 0.  Batch stride is 2048*2048 = multiple of both, so
// the same mask covers all batches.

__device__ float g_a;
__device__ float g_b;  // already multiplied by 256

__global__ void scalars_kernel(const float* __restrict__ conv_w,
                               const float* __restrict__ conv_b,
                               const float* __restrict__ out_w,
                               const float* __restrict__ out_b) {
    if (threadIdx.x == 0) {
        float a = 0.f, b = 0.f;
#pragma unroll
        for (int c = 0; c < 16; ++c) {
            a += conv_w[c] * out_w[c];
            b += conv_b[c] * out_w[c];
        }
        g_a = a;
        g_b = 256.0f * (b + out_b[0]);
    }
}

// 4 * 2048 * 2048 = 16,777,216 elements = 4,194,304 float4s.
// One float4 per thread, exact grid: pure HBM-streaming kernel.
__global__ void __launch_bounds__(256) scale_kernel(const float4* __restrict__ in,
                                                    float4* __restrict__ out) {
    const int i = blockIdx.x * blockDim.x + threadIdx.x;
    const float a = g_a;
    float4 v = in[i];
    v.x *= a;
    v.y *= a;
    v.z *= a;
    v.w *= a;
    const int e = i << 2;
    if ((e & 0x7F8FF) == 0) {
        v.x += g_b;
    }
    out[i] = v;
}

extern "C" void kernel_launch(void* const* d_in, const int* in_sizes, int n_in,
                              void* d_out, int out_size) {
    const float* x      = (const float*)d_in[0];
    const float* conv_w = (const float*)d_in[1];
    const float* conv_b = (const float*)d_in[2];
    const float* out_w  = (const float*)d_in[3];
    const float* out_b  = (const float*)d_in[4];
    float* out = (float*)d_out;

    scalars_kernel<<<1, 32>>>(conv_w, conv_b, out_w, out_b);

    const int n4 = out_size / 4;          // 4,194,304
    const int threads = 256;
    const int blocks = n4 / threads;      // 16,384
    scale_kernel<<<blocks, threads>>>((const float4*)x, (float4*)out);
}

// round 2
// speedup vs baseline: 1.2771x; 1.2771x over previous
#include <cuda_runtime.h>

// Analytic collapse of the reference:
//   channel block is affine: y = a*Hadamard2D(x) + b, with
//     a = dot(out_w, conv_w), b = dot(out_w, conv_b) + out_b
//   _H_MAT is symmetric and _H_MAT @ _H_MAT = I, so applying the 2-D
//   transform twice is identity, and the constant term transforms to
//   H J H^T = P * e0 e0^T per 256x256 patch:
//     out[e] = a*x[e] + 256*b at patch corners (h%256==0 && w%256==0).
// With W=2048 the corner condition on the flat index e is (e & 0x7F8FF)==0;
// batch stride (2048*2048) is a multiple, so one mask covers all batches.
//
// Single fused kernel:
//  - thread 0 of each block computes (a, 256*b) from the 49 tiny weights
//    (uniform, L1/L2-hit) into shared memory -> no separate scalar kernel.
//  - each thread streams 4 float4s (MLP=4) for latency hiding.
//  - input read with __ldcg (L2-resident across graph replays, skip L1);
//    output written with __stcs (evict-first streaming) so the 67MB input
//    stays pinned in the 126MB L2 while writes stream to HBM.

__global__ void __launch_bounds__(256)
fused_scale_kernel(const float4* __restrict__ in,
                   float4* __restrict__ out,
                   const float* __restrict__ conv_w,
                   const float* __restrict__ conv_b,
                   const float* __restrict__ out_w,
                   const float* __restrict__ out_b) {
    __shared__ float s_a, s_b;
    if (threadIdx.x == 0) {
        float a = 0.f, b = 0.f;
#pragma unroll
        for (int c = 0; c < 16; ++c) {
            a += conv_w[c] * out_w[c];
            b += conv_b[c] * out_w[c];
        }
        s_a = a;
        s_b = 256.0f * (b + out_b[0]);
    }
    __syncthreads();
    const float a = s_a;
    const float bb = s_b;

    // Block tile: 4 * 256 = 1024 float4s, coalesced (stride 256 per step).
    const int base = blockIdx.x * 1024 + threadIdx.x;

    float4 v[4];
#pragma unroll
    for (int j = 0; j < 4; ++j) {
        v[j] = __ldcg(&in[base + j * 256]);
    }
#pragma unroll
    for (int j = 0; j < 4; ++j) {
        v[j].x *= a;
        v[j].y *= a;
        v[j].z *= a;
        v[j].w *= a;
        const int e = (base + j * 256) << 2;  // flat element index
        if ((e & 0x7F8FF) == 0) {
            v[j].x += bb;
        }
    }
#pragma unroll
    for (int j = 0; j < 4; ++j) {
        __stcs(&out[base + j * 256], v[j]);
    }
}

extern "C" void kernel_launch(void* const* d_in, const int* in_sizes, int n_in,
                              void* d_out, int out_size) {
    const float* x      = (const float*)d_in[0];
    const float* conv_w = (const float*)d_in[1];
    const float* conv_b = (const float*)d_in[2];
    const float* out_w  = (const float*)d_in[3];
    const float* out_b  = (const float*)d_in[4];
    float* out = (float*)d_out;

    const int n4 = out_size / 4;        // 4,194,304 float4s
    const int blocks = n4 / 1024;       // 4096 blocks, 4 float4s/thread
    fused_scale_kernel<<<blocks, 256>>>((const float4*)x, (float4*)out,
                                        conv_w, conv_b, out_w, out_b);
}

// round 3
// speedup vs baseline: 1.2947x; 1.0137x over previous
#include <cuda_runtime.h>

// Analytic collapse of the reference:
//   channel block is affine: y = a*Hadamard2D(x) + b, with
//     a = dot(out_w, conv_w), b = dot(out_w, conv_b) + out_b
//   _H_MAT is symmetric and _H_MAT @ _H_MAT = I, so the double 2-D transform
//   is identity and the constant transforms to H J H^T = 256 * e0 e0^T:
//     out[e] = a*x[e] + 256*b at patch corners (h%256==0 && w%256==0).
// With W=2048 the corner condition on the flat element index e is
// (e & 0x7F8FF) == 0 (covers all batches; batch stride is a multiple).
//
// R2 lesson: the per-block thread-0 + __syncthreads scalar prologue
// serialized each (short-lived) block. Now every thread computes the two
// scalars itself via __ldg (broadcast L1/L2 hits, 32 FFMA — free), and the
// 8 streaming loads are issued FIRST so the scalar math hides under their
// latency. No shared memory, no barrier.

__global__ void __launch_bounds__(256)
fused_scale_kernel(const float4* __restrict__ in,
                   float4* __restrict__ out,
                   const float* __restrict__ conv_w,
                   const float* __restrict__ conv_b,
                   const float* __restrict__ out_w,
                   const float* __restrict__ out_b) {
    // Block tile: 8 * 256 = 2048 float4s, coalesced (stride 256 per step).
    const int base = blockIdx.x * 2048 + threadIdx.x;

    // Front-batched streaming loads (MLP=8).
    float4 v[8];
#pragma unroll
    for (int j = 0; j < 8; ++j) {
        v[j] = __ldcg(&in[base + j * 256]);
    }

    // Scalars, computed redundantly per thread (uniform broadcast loads),
    // overlapping the streaming-load latency.
    float a = 0.f, b = 0.f;
#pragma unroll
    for (int c = 0; c < 16; ++c) {
        a += __ldg(&conv_w[c]) * __ldg(&out_w[c]);
        b += __ldg(&conv_b[c]) * __ldg(&out_w[c]);
    }
    const float bb = 256.0f * (b + __ldg(&out_b[0]));

#pragma unroll
    for (int j = 0; j < 8; ++j) {
        v[j].x *= a;
        v[j].y *= a;
        v[j].z *= a;
        v[j].w *= a;
        const int e = (base + j * 256) << 2;  // flat element index
        if ((e & 0x7F8FF) == 0) {
            v[j].x += bb;
        }
        __stcs(&out[base + j * 256], v[j]);
    }
}

extern "C" void kernel_launch(void* const* d_in, const int* in_sizes, int n_in,
                              void* d_out, int out_size) {
    const float* x      = (const float*)d_in[0];
    const float* conv_w = (const float*)d_in[1];
    const float* conv_b = (const float*)d_in[2];
    const float* out_w  = (const float*)d_in[3];
    const float* out_b  = (const float*)d_in[4];
    float* out = (float*)d_out;

    const int n4 = out_size / 4;        // 4,194,304 float4s
    const int blocks = n4 / 2048;       // 2048 blocks, 8 float4s/thread
    fused_scale_kernel<<<blocks, 256>>>((const float4*)x, (float4*)out,
                                        conv_w, conv_b, out_w, out_b);
}

// round 4
// speedup vs baseline: 1.4324x; 1.1064x over previous
#include <cuda_runtime.h>

// Analytic collapse of the reference:
//   channel block is affine: y = a*Hadamard2D(x) + b, with
//     a = dot(out_w, conv_w), b = dot(out_w, conv_b) + out_b
//   _H_MAT is symmetric and _H_MAT @ _H_MAT = I, so the double 2-D transform
//   is identity and the constant transforms to H J H^T = 256 * e0 e0^T:
//     out[e] = a*x[e] + 256*b at patch corners (h%256==0 && w%256==0).
// With W=2048 the corner condition on the flat element index e is
// (e & 0x7F8FF) == 0 (covers all batches; batch stride is a multiple).
//
// R3 lesson: 2048 short-lived blocks in ~2 ragged waves + occ 58% left every
// roofline counter under 55% — latency/spread bound, not bandwidth bound.
// Now: persistent single-wave grid (148 SMs x 8 blocks x 256 thr = full
// occupancy for the whole kernel), grid-stride loop, x4 unroll for MLP.

#ifndef NUM_SMS
#define NUM_SMS 148
#endif
#define BLOCKS (NUM_SMS * 8)
#define THREADS 256
#define N4 (4 * 2048 * 2048 / 4)  // 4,194,304 float4s

__global__ void __launch_bounds__(THREADS, 8)
fused_scale_kernel(const float4* __restrict__ in,
                   float4* __restrict__ out,
                   const float* __restrict__ conv_w,
                   const float* __restrict__ conv_b,
                   const float* __restrict__ out_w,
                   const float* __restrict__ out_b) {
    const int stride = BLOCKS * THREADS;  // 303,104
    int i = blockIdx.x * THREADS + threadIdx.x;

    // Scalars, computed redundantly per thread (uniform broadcast loads).
    float a = 0.f, b = 0.f;
#pragma unroll
    for (int c = 0; c < 16; ++c) {
        a += __ldg(&conv_w[c]) * __ldg(&out_w[c]);
        b += __ldg(&conv_b[c]) * __ldg(&out_w[c]);
    }
    const float bb = 256.0f * (b + __ldg(&out_b[0]));

    // Main loop: 4 independent float4 streams per iteration (MLP=4).
    for (; i + 3 * stride < N4; i += 4 * stride) {
        float4 v[4];
#pragma unroll
        for (int j = 0; j < 4; ++j) {
            v[j] = __ldcg(&in[i + j * stride]);
        }
#pragma unroll
        for (int j = 0; j < 4; ++j) {
            v[j].x *= a;
            v[j].y *= a;
            v[j].z *= a;
            v[j].w *= a;
            const int e = (i + j * stride) << 2;  // flat element index
            if ((e & 0x7F8FF) == 0) {
                v[j].x += bb;
            }
            __stcs(&out[i + j * stride], v[j]);
        }
    }
    // Remainder (13.84 iters/thread -> up to 2 leftover).
    for (; i < N4; i += stride) {
        float4 v = __ldcg(&in[i]);
        v.x *= a;
        v.y *= a;
        v.z *= a;
        v.w *= a;
        const int e = i << 2;
        if ((e & 0x7F8FF) == 0) {
            v.x += bb;
        }
        __stcs(&out[i], v);
    }
}

extern "C" void kernel_launch(void* const* d_in, const int* in_sizes, int n_in,
                              void* d_out, int out_size) {
    const float* x      = (const float*)d_in[0];
    const float* conv_w = (const float*)d_in[1];
    const float* conv_b = (const float*)d_in[2];
    const float* out_w  = (const float*)d_in[3];
    const float* out_b  = (const float*)d_in[4];
    float* out = (float*)d_out;

    fused_scale_kernel<<<BLOCKS, THREADS>>>((const float4*)x, (float4*)out,
                                            conv_w, conv_b, out_w, out_b);
}